// round 7
// baseline (speedup 1.0000x reference)
#include <cuda_runtime.h>
#include <cuda_fp16.h>
#include <cstdint>

// Problem constants
#define MM      16
#define NN      8192
#define KK      8192
#define GROUPK  128
#define SPLITK  8
#define CHUNK   1024   // K per split = KK/SPLITK

// Static device scratch (no allocation allowed)
__device__ float  g_part[SPLITK * MM * NN];        // 4 MB split-K partials
__device__ __half g_xh[MM * KK];                   // 256 KB normalized x (fp16)
__device__ float  g_scalesf[(KK / GROUPK) * NN];   // 2 MB normalized scales (fp32)
__device__ float  g_biasf[NN];                     // 32 KB normalized bias (fp32)
__device__ int    g_dtype;                         // 0=fp16, 1=bf16, 2=fp32

// ---------------------------------------------------------------------------
// Classify the storage dtype of x by bit-pattern statistics over 128 words.
//  - word-test: both 16-bit halves have bits[14:7] in [100,135]
//      fp32 data : ~18/128 pass (low half = uniform mantissa bits)
//      fp16 data : ~90/128 pass
//      bf16 data : ~126/128 pass
//  - half-test: fp16-decoded |v| < 0.25 (exp5 <= 12)
//      fp16 data : ~59/256    bf16 data : ~0/256
// ---------------------------------------------------------------------------
__global__ void classify_kernel(const unsigned* __restrict__ xw)
{
    __shared__ int s_lofl, s_small;
    if (threadIdx.x == 0) { s_lofl = 0; s_small = 0; }
    __syncthreads();

    const unsigned w = xw[threadIdx.x];         // 128 threads, 1 word each
    const int e_lo = (w >> 7)  & 0xFF;
    const int e_hi = (w >> 23) & 0xFF;
    if (e_lo >= 100 && e_lo <= 135 && e_hi >= 100 && e_hi <= 135)
        atomicAdd(&s_lofl, 1);

    int sm = 0;
    const int e5a = (w >> 10) & 0x1F;
    const int e5b = (w >> 26) & 0x1F;
    if (e5a <= 12) ++sm;
    if (e5b <= 12) ++sm;
    if (sm) atomicAdd(&s_small, sm);
    __syncthreads();

    if (threadIdx.x == 0) {
        int dt;
        if (s_lofl < 55)        dt = 2;              // fp32
        else if (s_small >= 13) dt = 0;              // fp16
        else                    dt = 1;              // bf16
        g_dtype = dt;
    }
}

// ---------------------------------------------------------------------------
// Normalize inputs: x -> fp16 scratch, scales/bias -> fp32 scratch.
// ---------------------------------------------------------------------------
__device__ __forceinline__ float load_as_float(const void* p, int i, int dt)
{
    if (dt == 2) return ((const float*)p)[i];
    if (dt == 1) {
        const unsigned short b = ((const unsigned short*)p)[i];
        return __uint_as_float(((unsigned)b) << 16);
    }
    return __half2float(((const __half*)p)[i]);
}

__global__ __launch_bounds__(256) void convert_kernel(
    const void* __restrict__ x, const void* __restrict__ sc,
    const void* __restrict__ bi)
{
    const int dt = g_dtype;
    const int stride = gridDim.x * blockDim.x;
    const int tid = blockIdx.x * blockDim.x + threadIdx.x;

    for (int i = tid; i < MM * KK; i += stride)
        g_xh[i] = __float2half(load_as_float(x, i, dt));
    for (int i = tid; i < (KK / GROUPK) * NN; i += stride)
        g_scalesf[i] = load_as_float(sc, i, dt);
    for (int i = tid; i < NN; i += stride)
        g_biasf[i] = load_as_float(bi, i, dt);
}

// ---------------------------------------------------------------------------
// Compute kernel: each warp computes a 16 x 32 output tile over one K-chunk.
// CTA = 4 warps -> 128 columns. grid = (NN/128, SPLITK).
// ---------------------------------------------------------------------------
__global__ __launch_bounds__(128) void quant_gemm_kernel(
    const unsigned* __restrict__ qw)     // [KK/8, NN] packed int4
{
    const int lane = threadIdx.x & 31;
    const int warp = threadIdx.x >> 5;
    const int lr   = lane >> 2;   // groupID: A/C row, B column within n8 tile
    const int lc   = lane & 3;    // thread-in-group
    const int shft = lc * 8;      // byte select within packed word

    const int nb = blockIdx.x * 128 + warp * 32;   // warp's N base
    const int k0 = blockIdx.y * CHUNK;             // split's K base
    const int split = blockIdx.y;

    const unsigned* xa = reinterpret_cast<const unsigned*>(g_xh);
    const __half2 off1032 = __half2half2(__ushort_as_half(0x6408)); // 1032.0

    float acc[16];
    #pragma unroll
    for (int i = 0; i < 16; ++i) acc[i] = 0.f;

    for (int g = 0; g < CHUNK / GROUPK; ++g) {   // 8 groups of 128 k
        float grp[16];
        #pragma unroll
        for (int i = 0; i < 16; ++i) grp[i] = 0.f;

        #pragma unroll
        for (int s = 0; s < GROUPK / 16; ++s) {  // 8 x k16 steps
            const int kb = k0 + g * GROUPK + s * 16;
            const int kk = kb >> 3;              // qweight row (8 k per word)

            // Coalesced B word loads: lane -> column nb+lane, rows kk, kk+1
            const unsigned w0 = __ldg(&qw[(size_t)kk * NN + nb + lane]);
            const unsigned w1 = __ldg(&qw[(size_t)(kk + 1) * NN + nb + lane]);

            // A fragment (16x16 tile), from normalized fp16 scratch
            const unsigned a0 = xa[(lr * KK + kb) / 2 + lc];
            const unsigned a1 = xa[((lr + 8) * KK + kb) / 2 + lc];
            const unsigned a2 = xa[(lr * KK + kb) / 2 + 4 + lc];
            const unsigned a3 = xa[((lr + 8) * KK + kb) / 2 + 4 + lc];

            #pragma unroll
            for (int i = 0; i < 4; ++i) {        // 4 x n8 tiles -> 32 columns
                const int src = 8 * i + lr;      // lane holding this column
                unsigned t0 = __shfl_sync(0xffffffffu, w0, src) >> shft;
                unsigned t1 = __shfl_sync(0xffffffffu, w1, src) >> shft;

                // two nibbles -> fp16x2 {1024+lo,1024+hi}; -1032 -> (nib-8)
                unsigned h0 = (t0 & 0xFu) | ((t0 << 12) & 0xF0000u) | 0x64006400u;
                unsigned h1 = (t1 & 0xFu) | ((t1 << 12) & 0xF0000u) | 0x64006400u;
                __half2 bh0 = __hsub2(*reinterpret_cast<__half2*>(&h0), off1032);
                __half2 bh1 = __hsub2(*reinterpret_cast<__half2*>(&h1), off1032);
                const unsigned b0 = *reinterpret_cast<unsigned*>(&bh0);
                const unsigned b1 = *reinterpret_cast<unsigned*>(&bh1);

                asm volatile(
                    "mma.sync.aligned.m16n8k16.row.col.f32.f16.f16.f32 "
                    "{%0,%1,%2,%3}, {%4,%5,%6,%7}, {%8,%9}, {%0,%1,%2,%3};\n"
                    : "+f"(grp[4 * i + 0]), "+f"(grp[4 * i + 1]),
                      "+f"(grp[4 * i + 2]), "+f"(grp[4 * i + 3])
                    : "r"(a0), "r"(a1), "r"(a2), "r"(a3), "r"(b0), "r"(b1));
            }
        }

        // Apply per-group scales (deferred): acc += grp * scale[g][col]
        const int gg = (k0 >> 7) + g;
        #pragma unroll
        for (int i = 0; i < 4; ++i) {
            const int cb = nb + 8 * i + lc * 2;  // this thread's two C columns
            const float2 sf = *reinterpret_cast<const float2*>(
                &g_scalesf[(size_t)gg * NN + cb]);
            acc[4 * i + 0] += grp[4 * i + 0] * sf.x;
            acc[4 * i + 1] += grp[4 * i + 1] * sf.y;
            acc[4 * i + 2] += grp[4 * i + 2] * sf.x;
            acc[4 * i + 3] += grp[4 * i + 3] * sf.y;
        }
    }

    // Store fp32 partials (each slot written exactly once)
    #pragma unroll
    for (int i = 0; i < 4; ++i) {
        const int cb = nb + 8 * i + lc * 2;
        float* p0 = &g_part[((size_t)split * MM + lr) * NN + cb];
        float* p1 = &g_part[((size_t)split * MM + lr + 8) * NN + cb];
        *reinterpret_cast<float2*>(p0) = make_float2(acc[4 * i + 0], acc[4 * i + 1]);
        *reinterpret_cast<float2*>(p1) = make_float2(acc[4 * i + 2], acc[4 * i + 3]);
    }
}

// ---------------------------------------------------------------------------
// Epilogue: sum SPLITK partials + bias -> FLOAT32 output
// ---------------------------------------------------------------------------
__global__ __launch_bounds__(256) void reduce_kernel(float* __restrict__ out)
{
    const int idx2 = blockIdx.x * blockDim.x + threadIdx.x;  // pair index
    const int idx  = idx2 * 2;                               // 0 .. MM*NN-2
    const int n    = idx & (NN - 1);

    float a0 = 0.f, a1 = 0.f;
    #pragma unroll
    for (int s = 0; s < SPLITK; ++s) {
        const float2 p = *reinterpret_cast<const float2*>(
            &g_part[(size_t)s * MM * NN + idx]);
        a0 += p.x;
        a1 += p.y;
    }
    *reinterpret_cast<float2*>(&out[idx]) =
        make_float2(a0 + g_biasf[n], a1 + g_biasf[n + 1]);
}

extern "C" void kernel_launch(void* const* d_in, const int* in_sizes, int n_in,
                              void* d_out, int out_size)
{
    // Bind inputs by UNIQUE element counts (order-proof):
    //   x: 131072, qweight: 8388608, scales: 524288, bias: 8192
    const void*     x      = nullptr;
    const unsigned* qw     = nullptr;
    const void*     scales = nullptr;
    const void*     bias   = nullptr;

    for (int i = 0; i < n_in; ++i) {
        switch (in_sizes[i]) {
            case MM * KK:            x      = d_in[i];                  break;
            case (KK / 8) * NN:      qw     = (const unsigned*)d_in[i]; break;
            case (KK / GROUPK) * NN: scales = d_in[i];                  break;
            case NN:                 bias   = d_in[i];                  break;
            default: break;
        }
    }
    if (!x || !qw || !scales || !bias) {
        x      = d_in[0];
        qw     = (const unsigned*)d_in[1];
        scales = d_in[2];
        bias   = d_in[3];
    }

    float* out = (float*)d_out;

    classify_kernel<<<1, 128>>>((const unsigned*)x);
    convert_kernel<<<1024, 256>>>(x, scales, bias);
    quant_gemm_kernel<<<dim3(NN / 128, SPLITK), 128>>>(qw);
    reduce_kernel<<<(MM * NN) / 512, 256>>>(out);
}

// round 8
// speedup vs baseline: 1.2569x; 1.2569x over previous
#include <cuda_runtime.h>
#include <cuda_fp16.h>
#include <cstdint>

// Problem constants
#define MM      16
#define NN      8192
#define KK      8192
#define GROUPK  128
#define SPLITK  8
#define CHUNK   1024   // K per split = KK/SPLITK
#define NSTEPS  (KK / 16)   // 512 k16 steps

// Static device scratch (no allocation allowed)
__device__ float  g_part[SPLITK * MM * NN];        // 4 MB split-K partials
__device__ uint4  g_xfrag[NSTEPS * 32];            // 256 KB A fragments (fp16x2 x4)
__device__ float  g_scalesf[(KK / GROUPK) * NN];   // 2 MB normalized scales (fp32)
__device__ float  g_biasf[NN];                     // 32 KB normalized bias (fp32)
__device__ int    g_dtype;                         // 0=fp16, 1=bf16, 2=fp32

// ---------------------------------------------------------------------------
// Classify the storage dtype of x by bit-pattern statistics over 128 words.
// ---------------------------------------------------------------------------
__global__ void classify_kernel(const unsigned* __restrict__ xw)
{
    __shared__ int s_lofl, s_small;
    if (threadIdx.x == 0) { s_lofl = 0; s_small = 0; }
    __syncthreads();

    const unsigned w = xw[threadIdx.x];         // 128 threads, 1 word each
    const int e_lo = (w >> 7)  & 0xFF;
    const int e_hi = (w >> 23) & 0xFF;
    if (e_lo >= 100 && e_lo <= 135 && e_hi >= 100 && e_hi <= 135)
        atomicAdd(&s_lofl, 1);

    int sm = 0;
    const int e5a = (w >> 10) & 0x1F;
    const int e5b = (w >> 26) & 0x1F;
    if (e5a <= 12) ++sm;
    if (e5b <= 12) ++sm;
    if (sm) atomicAdd(&s_small, sm);
    __syncthreads();

    if (threadIdx.x == 0) {
        int dt;
        if (s_lofl < 55)        dt = 2;              // fp32
        else if (s_small >= 13) dt = 0;              // fp16
        else                    dt = 1;              // bf16
        g_dtype = dt;
    }
}

__device__ __forceinline__ float load_as_float(const void* p, int i, int dt)
{
    if (dt == 2) return ((const float*)p)[i];
    if (dt == 1) {
        const unsigned short b = ((const unsigned short*)p)[i];
        return __uint_as_float(((unsigned)b) << 16);
    }
    return __half2float(((const __half*)p)[i]);
}

// ---------------------------------------------------------------------------
// Convert: scales/bias -> fp32 scratch; x -> A-fragment-major fp16 layout.
// Fragment layout: for k16-step t and lane l, g_xfrag[t*32+l] = {a0,a1,a2,a3}
// per the mma.m16n8k16 A-fragment mapping (row lr / lr+8, k-pairs at 2*lc).
// ---------------------------------------------------------------------------
__global__ __launch_bounds__(256) void convert_kernel(
    const void* __restrict__ x, const void* __restrict__ sc,
    const void* __restrict__ bi)
{
    const int dt  = g_dtype;
    const int tid = blockIdx.x * blockDim.x + threadIdx.x;

    // A fragments: 512 steps * 32 lanes = 16384 threads
    if (tid < NSTEPS * 32) {
        const int t    = tid >> 5;
        const int lane = tid & 31;
        const int lr   = lane >> 2;
        const int lc   = lane & 3;
        const int kb   = t * 16;

        const int r0 = lr * KK, r1 = (lr + 8) * KK;
        const int ka = kb + 2 * lc;       // b0/b-low k-pair
        const int kc = kb + 8 + 2 * lc;   // high k-pair

        __half2 h0 = __floats2half2_rn(load_as_float(x, r0 + ka, dt),
                                       load_as_float(x, r0 + ka + 1, dt));
        __half2 h1 = __floats2half2_rn(load_as_float(x, r1 + ka, dt),
                                       load_as_float(x, r1 + ka + 1, dt));
        __half2 h2 = __floats2half2_rn(load_as_float(x, r0 + kc, dt),
                                       load_as_float(x, r0 + kc + 1, dt));
        __half2 h3 = __floats2half2_rn(load_as_float(x, r1 + kc, dt),
                                       load_as_float(x, r1 + kc + 1, dt));
        uint4 v;
        v.x = *reinterpret_cast<unsigned*>(&h0);
        v.y = *reinterpret_cast<unsigned*>(&h1);
        v.z = *reinterpret_cast<unsigned*>(&h2);
        v.w = *reinterpret_cast<unsigned*>(&h3);
        g_xfrag[tid] = v;
    }

    // scales: 524288 elements
    if (tid < (KK / GROUPK) * NN)
        g_scalesf[tid] = load_as_float(sc, tid, dt);

    // bias: 8192 elements
    if (tid < NN)
        g_biasf[tid] = load_as_float(bi, tid, dt);
}

// ---------------------------------------------------------------------------
// Compute kernel: each warp computes a 16 x 32 output tile over one K-chunk.
// CTA = 4 warps -> 128 columns. grid = (NN/128, SPLITK).
// ---------------------------------------------------------------------------
__global__ __launch_bounds__(128) void quant_gemm_kernel(
    const unsigned* __restrict__ qw)     // [KK/8, NN] packed int4
{
    const int lane = threadIdx.x & 31;
    const int warp = threadIdx.x >> 5;
    const int lr   = lane >> 2;
    const int lc   = lane & 3;
    const int shft = lc * 8;

    const int nb = blockIdx.x * 128 + warp * 32;   // warp's N base
    const int k0 = blockIdx.y * CHUNK;             // split's K base
    const int split = blockIdx.y;
    const int t0 = k0 >> 4;                        // first k16-step of split

    const __half2 off1032 = __half2half2(__ushort_as_half(0x6408)); // 1032.0

    float acc[16];
    #pragma unroll
    for (int i = 0; i < 16; ++i) acc[i] = 0.f;

    for (int g = 0; g < CHUNK / GROUPK; ++g) {   // 8 groups of 128 k
        float grp[16];
        #pragma unroll
        for (int i = 0; i < 16; ++i) grp[i] = 0.f;

        #pragma unroll
        for (int s = 0; s < GROUPK / 16; ++s) {  // 8 x k16 steps
            const int kb = k0 + g * GROUPK + s * 16;
            const int kk = kb >> 3;              // qweight row (8 k per word)

            // Coalesced B word loads: lane -> column nb+lane, rows kk, kk+1
            const unsigned w0 = __ldg(&qw[(size_t)kk * NN + nb + lane]);
            const unsigned w1 = __ldg(&qw[(size_t)(kk + 1) * NN + nb + lane]);

            // A fragment: one coalesced 16B load from fragment-major layout
            const uint4 av = g_xfrag[(t0 + g * 8 + s) * 32 + lane];

            #pragma unroll
            for (int i = 0; i < 4; ++i) {        // 4 x n8 tiles -> 32 columns
                const int src = 8 * i + lr;      // lane holding this column
                unsigned t0w = __shfl_sync(0xffffffffu, w0, src) >> shft;
                unsigned t1w = __shfl_sync(0xffffffffu, w1, src) >> shft;

                // two nibbles -> fp16x2 {1024+lo,1024+hi}; -1032 -> (nib-8)
                unsigned h0 = (t0w & 0xFu) | ((t0w << 12) & 0xF0000u) | 0x64006400u;
                unsigned h1 = (t1w & 0xFu) | ((t1w << 12) & 0xF0000u) | 0x64006400u;
                __half2 bh0 = __hsub2(*reinterpret_cast<__half2*>(&h0), off1032);
                __half2 bh1 = __hsub2(*reinterpret_cast<__half2*>(&h1), off1032);
                const unsigned b0 = *reinterpret_cast<unsigned*>(&bh0);
                const unsigned b1 = *reinterpret_cast<unsigned*>(&bh1);

                asm volatile(
                    "mma.sync.aligned.m16n8k16.row.col.f32.f16.f16.f32 "
                    "{%0,%1,%2,%3}, {%4,%5,%6,%7}, {%8,%9}, {%0,%1,%2,%3};\n"
                    : "+f"(grp[4 * i + 0]), "+f"(grp[4 * i + 1]),
                      "+f"(grp[4 * i + 2]), "+f"(grp[4 * i + 3])
                    : "r"(av.x), "r"(av.y), "r"(av.z), "r"(av.w),
                      "r"(b0), "r"(b1));
            }
        }

        // Apply per-group scales (deferred): acc += grp * scale[g][col]
        const int gg = (k0 >> 7) + g;
        #pragma unroll
        for (int i = 0; i < 4; ++i) {
            const int cb = nb + 8 * i + lc * 2;  // this thread's two C columns
            const float2 sf = *reinterpret_cast<const float2*>(
                &g_scalesf[(size_t)gg * NN + cb]);
            acc[4 * i + 0] += grp[4 * i + 0] * sf.x;
            acc[4 * i + 1] += grp[4 * i + 1] * sf.y;
            acc[4 * i + 2] += grp[4 * i + 2] * sf.x;
            acc[4 * i + 3] += grp[4 * i + 3] * sf.y;
        }
    }

    // Store fp32 partials (each slot written exactly once)
    #pragma unroll
    for (int i = 0; i < 4; ++i) {
        const int cb = nb + 8 * i + lc * 2;
        float* p0 = &g_part[((size_t)split * MM + lr) * NN + cb];
        float* p1 = &g_part[((size_t)split * MM + lr + 8) * NN + cb];
        *reinterpret_cast<float2*>(p0) = make_float2(acc[4 * i + 0], acc[4 * i + 1]);
        *reinterpret_cast<float2*>(p1) = make_float2(acc[4 * i + 2], acc[4 * i + 3]);
    }
}

// ---------------------------------------------------------------------------
// Epilogue: sum SPLITK partials + bias -> FLOAT32 output.
// One output per thread (131072 threads) for maximum memory-level parallelism.
// ---------------------------------------------------------------------------
__global__ __launch_bounds__(256) void reduce_kernel(float* __restrict__ out)
{
    const int idx = blockIdx.x * blockDim.x + threadIdx.x;  // 0 .. MM*NN-1
    const int n   = idx & (NN - 1);

    float a = 0.f;
    #pragma unroll
    for (int s = 0; s < SPLITK; ++s)
        a += __ldg(&g_part[(size_t)s * MM * NN + idx]);
    out[idx] = a + g_biasf[n];
}

extern "C" void kernel_launch(void* const* d_in, const int* in_sizes, int n_in,
                              void* d_out, int out_size)
{
    // Bind inputs by UNIQUE element counts (order-proof):
    //   x: 131072, qweight: 8388608, scales: 524288, bias: 8192
    const void*     x      = nullptr;
    const unsigned* qw     = nullptr;
    const void*     scales = nullptr;
    const void*     bias   = nullptr;

    for (int i = 0; i < n_in; ++i) {
        switch (in_sizes[i]) {
            case MM * KK:            x      = d_in[i];                  break;
            case (KK / 8) * NN:      qw     = (const unsigned*)d_in[i]; break;
            case (KK / GROUPK) * NN: scales = d_in[i];                  break;
            case NN:                 bias   = d_in[i];                  break;
            default: break;
        }
    }
    if (!x || !qw || !scales || !bias) {
        x      = d_in[0];
        qw     = (const unsigned*)d_in[1];
        scales = d_in[2];
        bias   = d_in[3];
    }

    float* out = (float*)d_out;

    classify_kernel<<<1, 128>>>((const unsigned*)x);
    convert_kernel<<<(KK / GROUPK) * NN / 256, 256>>>(x, scales, bias);
    quant_gemm_kernel<<<dim3(NN / 128, SPLITK), 128>>>(qw);
    reduce_kernel<<<(MM * NN) / 256, 256>>>(out);
}